// round 14
// baseline (speedup 1.0000x reference)
#include <cuda_runtime.h>
#include <cstdint>

// R14: R9 (best, 12.6us) with ONE change — map CTA count 400 -> 800 (chunks/CTA
// 8 -> 4). Same 8KB copies, same 2-stage/32KB pipeline, still a single wave.
// Widens TMA queue concurrency per SM instead of per-CTA depth (R12: neutral).
typedef unsigned long long u64;

#define Wd   320
#define Hd   320
#define Bd   64
#define Nd   32
#define HWd  (Hd * Wd)          // 102400
#define TOTd (Bd * HWd)         // 6553600
#define Md   (Nd * 5)           // 160
#define BMd  (Bd * Md)          // 10240

#define BLOCK    256
#define CHUNK_F  2048           // floats per stream per chunk (8KB)
#define CHUNK_B  (CHUNK_F * 4)  // 8192 bytes
#define NCHUNKS  (TOTd / CHUNK_F)      // 3200
#define MAP_GRID 800
#define CPC      (NCHUNKS / MAP_GRID)  // 4 chunks per CTA
#define BOX_GRID 40
#define TOTAL_GRID (MAP_GRID + BOX_GRID)
#define STAGES   2

// partA: [bce_sum, pt_sum, p_sum, t_sum]
// partB: [neg_log_iou_sum, reg_sum, one_m_giou_sum, conf_bce_sum]
__device__ float4 g_partA[MAP_GRID];
__device__ float4 g_partB[BOX_GRID];
__device__ int    g_count = 0;

// ---------------- packed f32x2 helpers (Blackwell) ----------------
__device__ __forceinline__ u64 addx2(u64 a, u64 b) {
    u64 r; asm("add.rn.f32x2 %0, %1, %2;" : "=l"(r) : "l"(a), "l"(b)); return r;
}
__device__ __forceinline__ u64 mulx2(u64 a, u64 b) {
    u64 r; asm("mul.rn.f32x2 %0, %1, %2;" : "=l"(r) : "l"(a), "l"(b)); return r;
}
__device__ __forceinline__ u64 fmax2(u64 a, u64 b, u64 c) {
    u64 r; asm("fma.rn.f32x2 %0, %1, %2, %3;" : "=l"(r) : "l"(a), "l"(b), "l"(c)); return r;
}
__device__ __forceinline__ void unpack2(u64 v, float& lo, float& hi) {
    asm("mov.b64 {%0, %1}, %2;" : "=f"(lo), "=f"(hi) : "l"(v));
}

// FMA-only natural log; <1 ulp for normal inputs.
__device__ __forceinline__ float ln_poly(float a) {
    int e = (__float_as_int(a) - 0x3f2aaaab) & 0xff800000;
    float m = __int_as_float(__float_as_int(a) - e);   // m in [2/3, 4/3)
    float i = (float)e * 1.19209290e-7f;               // e * 2^-23
    m = m - 1.0f;
    float s = m * m;
    float r = -0.130310059f;
    float t =  0.140869141f;
    r = fmaf(r, s, -0.121483512f);
    t = fmaf(t, s,  0.139814854f);
    r = fmaf(r, s, -0.166846126f);
    t = fmaf(t, s,  0.200120345f);
    r = fmaf(r, s, -0.249996200f);
    r = fmaf(t, m, r);
    r = fmaf(r, m,  0.333331972f);
    r = fmaf(r, m, -0.5f);
    r = fmaf(r, s, m);
    r = fmaf(i, 0.693147182f, r);
    return r;
}

__device__ __forceinline__ float warp_red_f(float v) {
    #pragma unroll
    for (int o = 16; o > 0; o >>= 1) v += __shfl_xor_sync(0xFFFFFFFFu, v, o);
    return v;
}
__device__ __forceinline__ float smooth_l1(float x) {
    float ax = fabsf(x);
    return (ax < 1.0f) ? 0.5f * ax * ax : ax - 0.5f;
}

__device__ __forceinline__ void block_reduce4(float v0, float v1, float v2, float v3,
                                              float4* dst) {
    __shared__ float sh[4][BLOCK / 32];
    int lane = threadIdx.x & 31, wid = threadIdx.x >> 5;
    v0 = warp_red_f(v0); v1 = warp_red_f(v1); v2 = warp_red_f(v2); v3 = warp_red_f(v3);
    if (lane == 0) { sh[0][wid] = v0; sh[1][wid] = v1; sh[2][wid] = v2; sh[3][wid] = v3; }
    __syncthreads();
    if (threadIdx.x == 0) {
        float a = 0, b = 0, c = 0, d = 0;
        #pragma unroll
        for (int w = 0; w < BLOCK / 32; w++) {
            a += sh[0][w]; b += sh[1][w]; c += sh[2][w]; d += sh[3][w];
        }
        *dst = make_float4(a, b, c, d);
    }
}

// mbarrier primitives (cta scope)
__device__ __forceinline__ uint32_t smem_u32(const void* p) {
    uint32_t a;
    asm("{ .reg .u64 t; cvta.to.shared.u64 t, %1; cvt.u32.u64 %0, t; }" : "=r"(a) : "l"(p));
    return a;
}
__device__ __forceinline__ void mbar_init(uint32_t mbar, uint32_t cnt) {
    asm volatile("mbarrier.init.shared.b64 [%0], %1;" :: "r"(mbar), "r"(cnt) : "memory");
}
__device__ __forceinline__ void mbar_expect_tx(uint32_t mbar, uint32_t bytes) {
    asm volatile("mbarrier.arrive.expect_tx.shared.b64 _, [%0], %1;" :: "r"(mbar), "r"(bytes) : "memory");
}
__device__ __forceinline__ void mbar_wait(uint32_t mbar, uint32_t phase) {
    uint32_t done = 0;
    while (!done) {
        asm volatile(
            "{ .reg .pred p;\n\t"
            "mbarrier.try_wait.parity.shared.b64 p, [%1], %2;\n\t"
            "selp.b32 %0, 1, 0, p; }"
            : "=r"(done) : "r"(mbar), "r"(phase) : "memory");
    }
}
__device__ __forceinline__ void bulk_g2s(uint32_t smem_dst, const void* gmem_src,
                                         uint32_t bytes, uint32_t mbar) {
    asm volatile(
        "cp.async.bulk.shared::cluster.global.mbarrier::complete_tx::bytes [%0], [%1], %2, [%3];"
        :: "r"(smem_dst), "l"(gmem_src), "r"(bytes), "r"(mbar) : "memory");
}

// BCE select: a = (1-p) + t*(2p-1), exact for t in {0,1}
#define BCE_SEL(t_, p_) fmax2(t_, fmax2(p_, TWOc, NEG1c), fmax2(p_, NEG1c, ONEc))

__global__ void __launch_bounds__(BLOCK)
fused_kernel(const float* __restrict__ pred, const float* __restrict__ tgt,
             const float* __restrict__ boxes, const float* __restrict__ bbox_coords,
             const float* __restrict__ confidence,
             float* __restrict__ out, int out_size) {
    __shared__ __align__(16) float smP[STAGES][CHUNK_F];
    __shared__ __align__(16) float smT[STAGES][CHUNK_F];
    __shared__ __align__(8)  unsigned long long mbar_store[STAGES];

    if (blockIdx.x < MAP_GRID) {
        const u64 TWOc  = 0x4000000040000000ull;
        const u64 NEG1c = 0xBF800000BF800000ull;
        const u64 ONEc  = 0x3F8000003F800000ull;

        uint32_t mb[STAGES];
        #pragma unroll
        for (int s2 = 0; s2 < STAGES; s2++) mb[s2] = smem_u32(&mbar_store[s2]);

        if (threadIdx.x == 0) {
            #pragma unroll
            for (int s2 = 0; s2 < STAGES; s2++) mbar_init(mb[s2], 1);
        }
        __syncthreads();

        const int c0 = blockIdx.x * CPC;       // first chunk of this CTA
        if (threadIdx.x == 0) {
            #pragma unroll
            for (int s2 = 0; s2 < STAGES; s2++) {
                mbar_expect_tx(mb[s2], 2 * CHUNK_B);
                bulk_g2s(smem_u32(&smP[s2][0]), pred + (size_t)(c0 + s2) * CHUNK_F,
                         CHUNK_B, mb[s2]);
                bulk_g2s(smem_u32(&smT[s2][0]), tgt + (size_t)(c0 + s2) * CHUNK_F,
                         CHUNK_B, mb[s2]);
            }
        }

        u64 sp = 0, st = 0, spt = 0;
        float sb = 0.0f;
        int phase[STAGES] = {0, 0};

        const int t2 = threadIdx.x;
        for (int c = 0; c < CPC; c++) {
            const int s2 = c & (STAGES - 1);
            mbar_wait(mb[s2], phase[s2]);
            phase[s2] ^= 1;

            const ulonglong2* pv = (const ulonglong2*)&smP[s2][0];
            const ulonglong2* tv = (const ulonglong2*)&smT[s2][0];
            // 512 ulonglong2 per stream; thread reads t2 and t2+256 (conflict-free)
            ulonglong2 P0 = pv[t2];
            ulonglong2 P1 = pv[t2 + 256];
            ulonglong2 T0 = tv[t2];
            ulonglong2 T1 = tv[t2 + 256];

            sp  = addx2(sp, addx2(addx2(P0.x, P0.y), addx2(P1.x, P1.y)));
            st  = addx2(st, addx2(addx2(T0.x, T0.y), addx2(T1.x, T1.y)));
            spt = fmax2(P0.x, T0.x, spt);
            spt = fmax2(P0.y, T0.y, spt);
            spt = fmax2(P1.x, T1.x, spt);
            spt = fmax2(P1.y, T1.y, spt);

            u64 a0 = BCE_SEL(T0.x, P0.x);
            u64 a1 = BCE_SEL(T0.y, P0.y);
            u64 a2 = BCE_SEL(T1.x, P1.x);
            u64 a3 = BCE_SEL(T1.y, P1.y);
            // product of 8 values in (1e-4,1): >= 1e-32, normal -> one log
            u64 m = mulx2(mulx2(a0, a1), mulx2(a2, a3));
            float lo, hi; unpack2(m, lo, hi);
            sb += ln_poly(lo * hi);

            __syncthreads();                   // all consumers done with stage s2
            const int cn = c + STAGES;
            if (cn < CPC && threadIdx.x == 0) {
                mbar_expect_tx(mb[s2], 2 * CHUNK_B);
                bulk_g2s(smem_u32(&smP[s2][0]), pred + (size_t)(c0 + cn) * CHUNK_F,
                         CHUNK_B, mb[s2]);
                bulk_g2s(smem_u32(&smT[s2][0]), tgt + (size_t)(c0 + cn) * CHUNK_F,
                         CHUNK_B, mb[s2]);
            }
        }
        float sp_l, sp_h, st_l, st_h, spt_l, spt_h;
        unpack2(sp, sp_l, sp_h); unpack2(st, st_l, st_h); unpack2(spt, spt_l, spt_h);
        block_reduce4(-sb, spt_l + spt_h, sp_l + sp_h, st_l + st_h, &g_partA[blockIdx.x]);
    } else {
        // ===== box + confidence loss at 10240 sample points =====
        const int s = (blockIdx.x - MAP_GRID) * BLOCK + threadIdx.x;
        int b  = s / Md;
        int r  = s - b * Md;
        int n  = r / 5;
        int pt = r - n * 5;
        const float* bx = boxes + (b * Nd + n) * 5;
        float tc  = bx[0];
        float nx1 = fminf(fmaxf(bx[1] * (1.0f / 320.0f), 0.0f), 0.999f);
        float ny1 = fminf(fmaxf(bx[2] * (1.0f / 320.0f), 0.0f), 0.999f);
        float nx2 = fmaxf(nx1 + 0.001f, fminf(bx[3] * (1.0f / 320.0f), 1.0f));
        float ny2 = fmaxf(ny1 + 0.001f, fminf(bx[4] * (1.0f / 320.0f), 1.0f));

        int x1p = min(max((int)(nx1 * 320.0f), 0), Wd - 1);
        int y1p = min(max((int)(ny1 * 320.0f), 0), Hd - 1);
        int x2p = max(x1p + 1, min((int)(nx2 * 320.0f), Wd - 1));
        int y2p = max(y1p + 1, min((int)(ny2 * 320.0f), Hd - 1));
        int cx = (x1p + x2p) >> 1;
        int cy = (y1p + y2p) >> 1;

        int xs, ys;
        switch (pt) {
            case 0: xs = cx;  ys = cy;  break;
            case 1: xs = x1p; ys = y1p; break;
            case 2: xs = x2p; ys = y1p; break;
            case 3: xs = x1p; ys = y2p; break;
            default: xs = x2p; ys = y2p; break;
        }
        int idx = ys * Wd + xs;

        const float* bc = bbox_coords + (size_t)b * 4 * HWd + idx;
        float g0 = __ldg(bc);
        float g1 = __ldg(bc + HWd);
        float g2 = __ldg(bc + 2 * HWd);
        float g3 = __ldg(bc + 3 * HWd);
        float gc = __ldg(confidence + (size_t)b * HWd + idx);

        float px1 = fminf(fmaxf(g0, 0.0f), 0.99f);
        float py1 = fminf(fmaxf(g1, 0.0f), 0.99f);
        float px2 = fminf(fmaxf(g2, 0.01f), 1.0f);
        float py2 = fminf(fmaxf(g3, 0.01f), 1.0f);
        float cx1 = fminf(px1, px2), cx2 = fmaxf(px1, px2);
        float cy1 = fminf(py1, py2), cy2 = fmaxf(py1, py2);

        float reg = smooth_l1(cx1 - nx1) + smooth_l1(cy1 - ny1)
                  + smooth_l1(cx2 - nx2) + smooth_l1(cy2 - ny2);

        float pa = (cx2 - cx1) * (cy2 - cy1);
        float ta = (nx2 - nx1) * (ny2 - ny1);
        float ix = fmaxf(fminf(cx2, nx2) - fmaxf(cx1, nx1), 0.0f);
        float iy = fmaxf(fminf(cy2, ny2) - fmaxf(cy1, ny1), 0.0f);
        float inter = ix * iy;
        float uni = pa + ta - inter;
        float iou = inter / (uni + 1e-6f);
        float ex = fmaxf(cx2, nx2) - fminf(cx1, nx1);
        float ey = fmaxf(cy2, ny2) - fminf(cy1, ny1);
        float enc = ex * ey;
        float giou = iou - (enc - uni) / (enc + 1e-6f);
        float nli = -ln_poly(iou + 1e-6f);
        float gi  = 1.0f - giou;

        float lg   = fmaxf(ln_poly(gc), -100.0f);
        float l1mg = fmaxf(ln_poly(1.0f - gc), -100.0f);
        float cb = -(tc * lg + (1.0f - tc) * l1mg);

        block_reduce4(nli, reg, gi, cb, &g_partB[blockIdx.x - MAP_GRID]);
    }

    // ===== last-block finalize (threadfence reduction, all-float) =====
    __shared__ bool isLast;
    if (threadIdx.x == 0) {
        __threadfence();
        int v = atomicAdd(&g_count, 1);
        isLast = (v == TOTAL_GRID - 1);
        if (isLast) g_count = 0;               // reset for next graph replay
    }
    __syncthreads();
    if (!isLast) return;
    __threadfence();

    float a0 = 0.f, a1 = 0.f, a2 = 0.f, a3 = 0.f;
    for (int i = threadIdx.x; i < MAP_GRID; i += BLOCK) {
        float4 v = g_partA[i];
        a0 += v.x; a1 += v.y; a2 += v.z; a3 += v.w;
    }
    float b0 = 0.f, b1 = 0.f, b2 = 0.f, b3 = 0.f;
    if (threadIdx.x < BOX_GRID) {
        float4 v = g_partB[threadIdx.x];
        b0 = v.x; b1 = v.y; b2 = v.z; b3 = v.w;
    }
    __shared__ float shf[8][BLOCK / 32];
    int lane = threadIdx.x & 31, wid = threadIdx.x >> 5;
    a0 = warp_red_f(a0); a1 = warp_red_f(a1); a2 = warp_red_f(a2); a3 = warp_red_f(a3);
    b0 = warp_red_f(b0); b1 = warp_red_f(b1); b2 = warp_red_f(b2); b3 = warp_red_f(b3);
    if (lane == 0) {
        shf[0][wid] = a0; shf[1][wid] = a1; shf[2][wid] = a2; shf[3][wid] = a3;
        shf[4][wid] = b0; shf[5][wid] = b1; shf[6][wid] = b2; shf[7][wid] = b3;
    }
    __syncthreads();
    for (int i = 4 + (int)threadIdx.x; i < out_size; i += BLOCK) out[i] = 0.0f;
    if (threadIdx.x == 0) {
        float S[8];
        #pragma unroll
        for (int k = 0; k < 8; k++) {
            float v = 0.f;
            #pragma unroll
            for (int w = 0; w < BLOCK / 32; w++) v += shf[k][w];
            S[k] = v;
        }
        double bce_mean = (double)S[0] / (double)TOTd;
        double dice = (2.0 * (double)S[1] + 1e-5) / ((double)S[2] + (double)S[3] + 1e-5);
        double tml = 0.5 * bce_mean + 0.5 * (1.0 - dice);
        double box = 0.5 * ((double)S[4] / (double)BMd)
                   + 0.3 * ((double)S[5] / (double)(BMd * 4))
                   + 0.2 * ((double)S[6] / (double)BMd);
        double cl = (double)S[7] / (double)BMd;
        double total = tml + 20.0 * box + 0.5 * cl;
        if (out_size > 0) out[0] = (float)total;
        if (out_size > 1) out[1] = (float)tml;
        if (out_size > 2) out[2] = (float)box;
        if (out_size > 3) out[3] = (float)cl;
    }
}

// Inputs (metadata order): text_map_pred, confidence, bbox_coords, text_map_tgt, boxes
extern "C" void kernel_launch(void* const* d_in, const int* in_sizes, int n_in,
                              void* d_out, int out_size) {
    const float* pred  = (const float*)d_in[0];
    const float* conf  = (const float*)d_in[1];
    const float* bbox  = (const float*)d_in[2];
    const float* tgt   = (const float*)d_in[3];
    const float* boxes = (const float*)d_in[4];
    (void)in_sizes; (void)n_in;

    fused_kernel<<<TOTAL_GRID, BLOCK>>>(
        pred, tgt, boxes, bbox, conf, (float*)d_out, out_size);
}

// round 15
// speedup vs baseline: 1.1839x; 1.1839x over previous
#include <cuda_runtime.h>
#include <cstdint>

// R15: champion (R9, 12.6us) re-land. Identical structure: 400 persistent map
// CTAs, 8KB bulk copies, 2-stage mbarrier ring, fused box loss, last-block
// float finalize. Only change: final chunks skip the dead sync+reissue.
typedef unsigned long long u64;

#define Wd   320
#define Hd   320
#define Bd   64
#define Nd   32
#define HWd  (Hd * Wd)          // 102400
#define TOTd (Bd * HWd)         // 6553600
#define Md   (Nd * 5)           // 160
#define BMd  (Bd * Md)          // 10240

#define BLOCK    256
#define CHUNK_F  2048           // floats per stream per chunk (8KB)
#define CHUNK_B  (CHUNK_F * 4)  // 8192 bytes
#define NCHUNKS  (TOTd / CHUNK_F)      // 3200
#define MAP_GRID 400
#define CPC      (NCHUNKS / MAP_GRID)  // 8 chunks per CTA
#define BOX_GRID 40
#define TOTAL_GRID (MAP_GRID + BOX_GRID)
#define STAGES   2

// partA: [bce_sum, pt_sum, p_sum, t_sum]
// partB: [neg_log_iou_sum, reg_sum, one_m_giou_sum, conf_bce_sum]
__device__ float4 g_partA[MAP_GRID];
__device__ float4 g_partB[BOX_GRID];
__device__ int    g_count = 0;

// ---------------- packed f32x2 helpers (Blackwell) ----------------
__device__ __forceinline__ u64 addx2(u64 a, u64 b) {
    u64 r; asm("add.rn.f32x2 %0, %1, %2;" : "=l"(r) : "l"(a), "l"(b)); return r;
}
__device__ __forceinline__ u64 mulx2(u64 a, u64 b) {
    u64 r; asm("mul.rn.f32x2 %0, %1, %2;" : "=l"(r) : "l"(a), "l"(b)); return r;
}
__device__ __forceinline__ u64 fmax2(u64 a, u64 b, u64 c) {
    u64 r; asm("fma.rn.f32x2 %0, %1, %2, %3;" : "=l"(r) : "l"(a), "l"(b), "l"(c)); return r;
}
__device__ __forceinline__ void unpack2(u64 v, float& lo, float& hi) {
    asm("mov.b64 {%0, %1}, %2;" : "=f"(lo), "=f"(hi) : "l"(v));
}

// FMA-only natural log; <1 ulp for normal inputs.
__device__ __forceinline__ float ln_poly(float a) {
    int e = (__float_as_int(a) - 0x3f2aaaab) & 0xff800000;
    float m = __int_as_float(__float_as_int(a) - e);   // m in [2/3, 4/3)
    float i = (float)e * 1.19209290e-7f;               // e * 2^-23
    m = m - 1.0f;
    float s = m * m;
    float r = -0.130310059f;
    float t =  0.140869141f;
    r = fmaf(r, s, -0.121483512f);
    t = fmaf(t, s,  0.139814854f);
    r = fmaf(r, s, -0.166846126f);
    t = fmaf(t, s,  0.200120345f);
    r = fmaf(r, s, -0.249996200f);
    r = fmaf(t, m, r);
    r = fmaf(r, m,  0.333331972f);
    r = fmaf(r, m, -0.5f);
    r = fmaf(r, s, m);
    r = fmaf(i, 0.693147182f, r);
    return r;
}

__device__ __forceinline__ float warp_red_f(float v) {
    #pragma unroll
    for (int o = 16; o > 0; o >>= 1) v += __shfl_xor_sync(0xFFFFFFFFu, v, o);
    return v;
}
__device__ __forceinline__ float smooth_l1(float x) {
    float ax = fabsf(x);
    return (ax < 1.0f) ? 0.5f * ax * ax : ax - 0.5f;
}

__device__ __forceinline__ void block_reduce4(float v0, float v1, float v2, float v3,
                                              float4* dst) {
    __shared__ float sh[4][BLOCK / 32];
    int lane = threadIdx.x & 31, wid = threadIdx.x >> 5;
    v0 = warp_red_f(v0); v1 = warp_red_f(v1); v2 = warp_red_f(v2); v3 = warp_red_f(v3);
    if (lane == 0) { sh[0][wid] = v0; sh[1][wid] = v1; sh[2][wid] = v2; sh[3][wid] = v3; }
    __syncthreads();
    if (threadIdx.x == 0) {
        float a = 0, b = 0, c = 0, d = 0;
        #pragma unroll
        for (int w = 0; w < BLOCK / 32; w++) {
            a += sh[0][w]; b += sh[1][w]; c += sh[2][w]; d += sh[3][w];
        }
        *dst = make_float4(a, b, c, d);
    }
}

// mbarrier primitives (cta scope)
__device__ __forceinline__ uint32_t smem_u32(const void* p) {
    uint32_t a;
    asm("{ .reg .u64 t; cvta.to.shared.u64 t, %1; cvt.u32.u64 %0, t; }" : "=r"(a) : "l"(p));
    return a;
}
__device__ __forceinline__ void mbar_init(uint32_t mbar, uint32_t cnt) {
    asm volatile("mbarrier.init.shared.b64 [%0], %1;" :: "r"(mbar), "r"(cnt) : "memory");
}
__device__ __forceinline__ void mbar_expect_tx(uint32_t mbar, uint32_t bytes) {
    asm volatile("mbarrier.arrive.expect_tx.shared.b64 _, [%0], %1;" :: "r"(mbar), "r"(bytes) : "memory");
}
__device__ __forceinline__ void mbar_wait(uint32_t mbar, uint32_t phase) {
    uint32_t done = 0;
    while (!done) {
        asm volatile(
            "{ .reg .pred p;\n\t"
            "mbarrier.try_wait.parity.shared.b64 p, [%1], %2;\n\t"
            "selp.b32 %0, 1, 0, p; }"
            : "=r"(done) : "r"(mbar), "r"(phase) : "memory");
    }
}
__device__ __forceinline__ void bulk_g2s(uint32_t smem_dst, const void* gmem_src,
                                         uint32_t bytes, uint32_t mbar) {
    asm volatile(
        "cp.async.bulk.shared::cluster.global.mbarrier::complete_tx::bytes [%0], [%1], %2, [%3];"
        :: "r"(smem_dst), "l"(gmem_src), "r"(bytes), "r"(mbar) : "memory");
}

// BCE select: a = (1-p) + t*(2p-1), exact for t in {0,1}
#define BCE_SEL(t_, p_) fmax2(t_, fmax2(p_, TWOc, NEG1c), fmax2(p_, NEG1c, ONEc))

__global__ void __launch_bounds__(BLOCK)
fused_kernel(const float* __restrict__ pred, const float* __restrict__ tgt,
             const float* __restrict__ boxes, const float* __restrict__ bbox_coords,
             const float* __restrict__ confidence,
             float* __restrict__ out, int out_size) {
    __shared__ __align__(16) float smP[STAGES][CHUNK_F];
    __shared__ __align__(16) float smT[STAGES][CHUNK_F];
    __shared__ __align__(8)  unsigned long long mbar_store[STAGES];

    if (blockIdx.x < MAP_GRID) {
        const u64 TWOc  = 0x4000000040000000ull;
        const u64 NEG1c = 0xBF800000BF800000ull;
        const u64 ONEc  = 0x3F8000003F800000ull;

        uint32_t mb[STAGES];
        #pragma unroll
        for (int s2 = 0; s2 < STAGES; s2++) mb[s2] = smem_u32(&mbar_store[s2]);

        if (threadIdx.x == 0) {
            #pragma unroll
            for (int s2 = 0; s2 < STAGES; s2++) mbar_init(mb[s2], 1);
        }
        __syncthreads();

        const int c0 = blockIdx.x * CPC;       // first chunk of this CTA
        if (threadIdx.x == 0) {
            #pragma unroll
            for (int s2 = 0; s2 < STAGES; s2++) {
                mbar_expect_tx(mb[s2], 2 * CHUNK_B);
                bulk_g2s(smem_u32(&smP[s2][0]), pred + (size_t)(c0 + s2) * CHUNK_F,
                         CHUNK_B, mb[s2]);
                bulk_g2s(smem_u32(&smT[s2][0]), tgt + (size_t)(c0 + s2) * CHUNK_F,
                         CHUNK_B, mb[s2]);
            }
        }

        u64 sp = 0, st = 0, spt = 0;
        float sb = 0.0f;
        int phase[STAGES] = {0, 0};

        const int t2 = threadIdx.x;
        for (int c = 0; c < CPC; c++) {
            const int s2 = c & (STAGES - 1);
            mbar_wait(mb[s2], phase[s2]);
            phase[s2] ^= 1;

            const ulonglong2* pv = (const ulonglong2*)&smP[s2][0];
            const ulonglong2* tv = (const ulonglong2*)&smT[s2][0];
            // 512 ulonglong2 per stream; thread reads t2 and t2+256 (conflict-free)
            ulonglong2 P0 = pv[t2];
            ulonglong2 P1 = pv[t2 + 256];
            ulonglong2 T0 = tv[t2];
            ulonglong2 T1 = tv[t2 + 256];

            sp  = addx2(sp, addx2(addx2(P0.x, P0.y), addx2(P1.x, P1.y)));
            st  = addx2(st, addx2(addx2(T0.x, T0.y), addx2(T1.x, T1.y)));
            spt = fmax2(P0.x, T0.x, spt);
            spt = fmax2(P0.y, T0.y, spt);
            spt = fmax2(P1.x, T1.x, spt);
            spt = fmax2(P1.y, T1.y, spt);

            u64 a0 = BCE_SEL(T0.x, P0.x);
            u64 a1 = BCE_SEL(T0.y, P0.y);
            u64 a2 = BCE_SEL(T1.x, P1.x);
            u64 a3 = BCE_SEL(T1.y, P1.y);
            // product of 8 values in (1e-4,1): >= 1e-32, normal -> one log
            u64 m = mulx2(mulx2(a0, a1), mulx2(a2, a3));
            float lo, hi; unpack2(m, lo, hi);
            sb += ln_poly(lo * hi);

            // reissue this stage for chunk c+STAGES (skip dead work on tail)
            const int cn = c + STAGES;
            if (cn < CPC) {
                __syncthreads();               // all consumers done with stage s2
                if (threadIdx.x == 0) {
                    mbar_expect_tx(mb[s2], 2 * CHUNK_B);
                    bulk_g2s(smem_u32(&smP[s2][0]), pred + (size_t)(c0 + cn) * CHUNK_F,
                             CHUNK_B, mb[s2]);
                    bulk_g2s(smem_u32(&smT[s2][0]), tgt + (size_t)(c0 + cn) * CHUNK_F,
                             CHUNK_B, mb[s2]);
                }
            }
        }
        float sp_l, sp_h, st_l, st_h, spt_l, spt_h;
        unpack2(sp, sp_l, sp_h); unpack2(st, st_l, st_h); unpack2(spt, spt_l, spt_h);
        block_reduce4(-sb, spt_l + spt_h, sp_l + sp_h, st_l + st_h, &g_partA[blockIdx.x]);
    } else {
        // ===== box + confidence loss at 10240 sample points =====
        const int s = (blockIdx.x - MAP_GRID) * BLOCK + threadIdx.x;
        int b  = s / Md;
        int r  = s - b * Md;
        int n  = r / 5;
        int pt = r - n * 5;
        const float* bx = boxes + (b * Nd + n) * 5;
        float tc  = bx[0];
        float nx1 = fminf(fmaxf(bx[1] * (1.0f / 320.0f), 0.0f), 0.999f);
        float ny1 = fminf(fmaxf(bx[2] * (1.0f / 320.0f), 0.0f), 0.999f);
        float nx2 = fmaxf(nx1 + 0.001f, fminf(bx[3] * (1.0f / 320.0f), 1.0f));
        float ny2 = fmaxf(ny1 + 0.001f, fminf(bx[4] * (1.0f / 320.0f), 1.0f));

        int x1p = min(max((int)(nx1 * 320.0f), 0), Wd - 1);
        int y1p = min(max((int)(ny1 * 320.0f), 0), Hd - 1);
        int x2p = max(x1p + 1, min((int)(nx2 * 320.0f), Wd - 1));
        int y2p = max(y1p + 1, min((int)(ny2 * 320.0f), Hd - 1));
        int cx = (x1p + x2p) >> 1;
        int cy = (y1p + y2p) >> 1;

        int xs, ys;
        switch (pt) {
            case 0: xs = cx;  ys = cy;  break;
            case 1: xs = x1p; ys = y1p; break;
            case 2: xs = x2p; ys = y1p; break;
            case 3: xs = x1p; ys = y2p; break;
            default: xs = x2p; ys = y2p; break;
        }
        int idx = ys * Wd + xs;

        const float* bc = bbox_coords + (size_t)b * 4 * HWd + idx;
        float g0 = __ldg(bc);
        float g1 = __ldg(bc + HWd);
        float g2 = __ldg(bc + 2 * HWd);
        float g3 = __ldg(bc + 3 * HWd);
        float gc = __ldg(confidence + (size_t)b * HWd + idx);

        float px1 = fminf(fmaxf(g0, 0.0f), 0.99f);
        float py1 = fminf(fmaxf(g1, 0.0f), 0.99f);
        float px2 = fminf(fmaxf(g2, 0.01f), 1.0f);
        float py2 = fminf(fmaxf(g3, 0.01f), 1.0f);
        float cx1 = fminf(px1, px2), cx2 = fmaxf(px1, px2);
        float cy1 = fminf(py1, py2), cy2 = fmaxf(py1, py2);

        float reg = smooth_l1(cx1 - nx1) + smooth_l1(cy1 - ny1)
                  + smooth_l1(cx2 - nx2) + smooth_l1(cy2 - ny2);

        float pa = (cx2 - cx1) * (cy2 - cy1);
        float ta = (nx2 - nx1) * (ny2 - ny1);
        float ix = fmaxf(fminf(cx2, nx2) - fmaxf(cx1, nx1), 0.0f);
        float iy = fmaxf(fminf(cy2, ny2) - fmaxf(cy1, ny1), 0.0f);
        float inter = ix * iy;
        float uni = pa + ta - inter;
        float iou = inter / (uni + 1e-6f);
        float ex = fmaxf(cx2, nx2) - fminf(cx1, nx1);
        float ey = fmaxf(cy2, ny2) - fminf(cy1, ny1);
        float enc = ex * ey;
        float giou = iou - (enc - uni) / (enc + 1e-6f);
        float nli = -ln_poly(iou + 1e-6f);
        float gi  = 1.0f - giou;

        float lg   = fmaxf(ln_poly(gc), -100.0f);
        float l1mg = fmaxf(ln_poly(1.0f - gc), -100.0f);
        float cb = -(tc * lg + (1.0f - tc) * l1mg);

        block_reduce4(nli, reg, gi, cb, &g_partB[blockIdx.x - MAP_GRID]);
    }

    // ===== last-block finalize (threadfence reduction, all-float) =====
    __shared__ bool isLast;
    if (threadIdx.x == 0) {
        __threadfence();
        int v = atomicAdd(&g_count, 1);
        isLast = (v == TOTAL_GRID - 1);
        if (isLast) g_count = 0;               // reset for next graph replay
    }
    __syncthreads();
    if (!isLast) return;
    __threadfence();

    float a0 = 0.f, a1 = 0.f, a2 = 0.f, a3 = 0.f;
    for (int i = threadIdx.x; i < MAP_GRID; i += BLOCK) {
        float4 v = g_partA[i];
        a0 += v.x; a1 += v.y; a2 += v.z; a3 += v.w;
    }
    float b0 = 0.f, b1 = 0.f, b2 = 0.f, b3 = 0.f;
    if (threadIdx.x < BOX_GRID) {
        float4 v = g_partB[threadIdx.x];
        b0 = v.x; b1 = v.y; b2 = v.z; b3 = v.w;
    }
    __shared__ float shf[8][BLOCK / 32];
    int lane = threadIdx.x & 31, wid = threadIdx.x >> 5;
    a0 = warp_red_f(a0); a1 = warp_red_f(a1); a2 = warp_red_f(a2); a3 = warp_red_f(a3);
    b0 = warp_red_f(b0); b1 = warp_red_f(b1); b2 = warp_red_f(b2); b3 = warp_red_f(b3);
    if (lane == 0) {
        shf[0][wid] = a0; shf[1][wid] = a1; shf[2][wid] = a2; shf[3][wid] = a3;
        shf[4][wid] = b0; shf[5][wid] = b1; shf[6][wid] = b2; shf[7][wid] = b3;
    }
    __syncthreads();
    for (int i = 4 + (int)threadIdx.x; i < out_size; i += BLOCK) out[i] = 0.0f;
    if (threadIdx.x == 0) {
        float S[8];
        #pragma unroll
        for (int k = 0; k < 8; k++) {
            float v = 0.f;
            #pragma unroll
            for (int w = 0; w < BLOCK / 32; w++) v += shf[k][w];
            S[k] = v;
        }
        double bce_mean = (double)S[0] / (double)TOTd;
        double dice = (2.0 * (double)S[1] + 1e-5) / ((double)S[2] + (double)S[3] + 1e-5);
        double tml = 0.5 * bce_mean + 0.5 * (1.0 - dice);
        double box = 0.5 * ((double)S[4] / (double)BMd)
                   + 0.3 * ((double)S[5] / (double)(BMd * 4))
                   + 0.2 * ((double)S[6] / (double)BMd);
        double cl = (double)S[7] / (double)BMd;
        double total = tml + 20.0 * box + 0.5 * cl;
        if (out_size > 0) out[0] = (float)total;
        if (out_size > 1) out[1] = (float)tml;
        if (out_size > 2) out[2] = (float)box;
        if (out_size > 3) out[3] = (float)cl;
    }
}

// Inputs (metadata order): text_map_pred, confidence, bbox_coords, text_map_tgt, boxes
extern "C" void kernel_launch(void* const* d_in, const int* in_sizes, int n_in,
                              void* d_out, int out_size) {
    const float* pred  = (const float*)d_in[0];
    const float* conf  = (const float*)d_in[1];
    const float* bbox  = (const float*)d_in[2];
    const float* tgt   = (const float*)d_in[3];
    const float* boxes = (const float*)d_in[4];
    (void)in_sizes; (void)n_in;

    fused_kernel<<<TOTAL_GRID, BLOCK>>>(
        pred, tgt, boxes, bbox, conf, (float*)d_out, out_size);
}